// round 1
// baseline (speedup 1.0000x reference)
#include <cuda_runtime.h>
#include <math.h>

// ---------------------------------------------------------------------------
// VQ-VAE forward, fp32 direct conv, NHWC.
// Outputs (float32, concatenated): y[128*128*128*3] | loss[1] | idx[128*256]
// ---------------------------------------------------------------------------

#define ACT_NONE 0
#define ACT_RELU 1
#define ACT_SIG  2

// ---- scratch (device globals; reused encoder<->decoder) ----
__device__ float  g_a1[128 * 64 * 64 * 32];    // enc1 out / dec3 out (16.78M)
__device__ float  g_a2[128 * 32 * 32 * 64];    // enc2 out / dec2 out ( 8.39M)
__device__ float  g_a3[128 * 16 * 16 * 128];   // enc3 out / dec1 out ( 4.19M)
__device__ float  g_z [128 * 16 * 16 * 64];    // enc4 out (z)
__device__ float  g_q [128 * 16 * 16 * 64];    // quantized
__device__ int    g_idx[128 * 256];
__device__ float  g_e2[512];
__device__ double g_loss;

static const int Y_SIZE   = 128 * 128 * 128 * 3;   // 6,291,456
static const int N_POS    = 128 * 16 * 16;          // 32,768
static const int Z_ELEMS  = N_POS * 64;             // 2,097,152

__device__ __forceinline__ float apply_act(float v, int ACT) {
    if (ACT == ACT_RELU) return fmaxf(v, 0.0f);
    if (ACT == ACT_SIG)  return 1.0f / (1.0f + expf(-v));
    return v;
}

// ---------------- forward conv (SAME), correlation, NHWC / HWIO ------------
// out[n,oy,ox,oc] = b[oc] + sum_{ky,kx,ic} in[n, oy*S-P+ky, ox*S-P+kx, ic] * w[ky,kx,ic,oc]
template<int K, int S, int P, int IC, int OC, int ACT, int IH, int IW, int OH, int OW, int VEC>
__global__ void conv_fwd(const float* __restrict__ in, const float* __restrict__ w,
                         const float* __restrict__ bias, float* __restrict__ out)
{
    constexpr int OCG = OC / VEC;
    constexpr int TOT = 128 * OH * OW * OCG;
    int t = blockIdx.x * blockDim.x + threadIdx.x;
    if (t >= TOT) return;

    int g   = t % OCG;  int tmp = t / OCG;
    int ox  = tmp % OW; tmp /= OW;
    int oy  = tmp % OH; int n = tmp / OH;
    int oc  = g * VEC;

    float acc[VEC];
#pragma unroll
    for (int j = 0; j < VEC; j++) acc[j] = bias[oc + j];

#pragma unroll
    for (int ky = 0; ky < K; ky++) {
        int iy = oy * S - P + ky;
        if ((unsigned)iy >= (unsigned)IH) continue;
#pragma unroll
        for (int kx = 0; kx < K; kx++) {
            int ix = ox * S - P + kx;
            if ((unsigned)ix >= (unsigned)IW) continue;
            const float* ip = in + (((n * IH + iy) * IW + ix) * IC);
            const float* wp = w + ((ky * K + kx) * IC) * OC + oc;
            if (VEC == 4) {
#pragma unroll 8
                for (int ic = 0; ic < IC; ic++) {
                    float iv = ip[ic];
                    float4 wv = *reinterpret_cast<const float4*>(wp + ic * OC);
                    acc[0] = fmaf(iv, wv.x, acc[0]);
                    acc[1] = fmaf(iv, wv.y, acc[1]);
                    acc[2] = fmaf(iv, wv.z, acc[2]);
                    acc[3] = fmaf(iv, wv.w, acc[3]);
                }
            } else {
#pragma unroll 8
                for (int ic = 0; ic < IC; ic++) {
                    float iv = ip[ic];
#pragma unroll
                    for (int j = 0; j < VEC; j++)
                        acc[j] = fmaf(iv, wp[ic * OC + j], acc[j]);
                }
            }
        }
    }

    int obase = ((n * OH + oy) * OW + ox) * OC + oc;
    if (VEC == 4) {
        float4 r;
        r.x = apply_act(acc[0], ACT); r.y = apply_act(acc[1], ACT);
        r.z = apply_act(acc[2], ACT); r.w = apply_act(acc[3], ACT);
        *reinterpret_cast<float4*>(out + obase) = r;
    } else {
#pragma unroll
        for (int j = 0; j < VEC; j++) out[obase + j] = apply_act(acc[j], ACT);
    }
}

// ---------------- transposed conv (lax.conv_transpose, SAME) ---------------
// correlation over stride-dilated input, pad_a applied at low edge:
// out[oy,ox,oc] = b[oc] + sum_{ky,kx,ic, (oy+ky-PA)%S==0, ...} in[(oy+ky-PA)/S, ...] * w[ky,kx,ic,oc]
template<int K, int S, int PA, int IC, int OC, int ACT, int IH, int IW, int OH, int OW, int VEC>
__global__ void convT_fwd(const float* __restrict__ in, const float* __restrict__ w,
                          const float* __restrict__ bias, float* __restrict__ out)
{
    constexpr int OCG = OC / VEC;
    constexpr int TOT = 128 * OH * OW * OCG;
    int t = blockIdx.x * blockDim.x + threadIdx.x;
    if (t >= TOT) return;

    int g   = t % OCG;  int tmp = t / OCG;
    int ox  = tmp % OW; tmp /= OW;
    int oy  = tmp % OH; int n = tmp / OH;
    int oc  = g * VEC;

    float acc[VEC];
#pragma unroll
    for (int j = 0; j < VEC; j++) acc[j] = bias[oc + j];

#pragma unroll
    for (int ky = 0; ky < K; ky++) {
        int py = oy + ky - PA;
        int iy;
        if (S == 2) { if (py & 1) continue; iy = py >> 1; } else { iy = py; }
        if ((unsigned)iy >= (unsigned)IH) continue;
#pragma unroll
        for (int kx = 0; kx < K; kx++) {
            int px = ox + kx - PA;
            int ix;
            if (S == 2) { if (px & 1) continue; ix = px >> 1; } else { ix = px; }
            if ((unsigned)ix >= (unsigned)IW) continue;
            const float* ip = in + (((n * IH + iy) * IW + ix) * IC);
            const float* wp = w + ((ky * K + kx) * IC) * OC + oc;
            if (VEC == 4) {
#pragma unroll 8
                for (int ic = 0; ic < IC; ic++) {
                    float iv = ip[ic];
                    float4 wv = *reinterpret_cast<const float4*>(wp + ic * OC);
                    acc[0] = fmaf(iv, wv.x, acc[0]);
                    acc[1] = fmaf(iv, wv.y, acc[1]);
                    acc[2] = fmaf(iv, wv.z, acc[2]);
                    acc[3] = fmaf(iv, wv.w, acc[3]);
                }
            } else {
#pragma unroll 8
                for (int ic = 0; ic < IC; ic++) {
                    float iv = ip[ic];
#pragma unroll
                    for (int j = 0; j < VEC; j++)
                        acc[j] = fmaf(iv, wp[ic * OC + j], acc[j]);
                }
            }
        }
    }

    int obase = ((n * OH + oy) * OW + ox) * OC + oc;
    if (VEC == 4) {
        float4 r;
        r.x = apply_act(acc[0], ACT); r.y = apply_act(acc[1], ACT);
        r.z = apply_act(acc[2], ACT); r.w = apply_act(acc[3], ACT);
        *reinterpret_cast<float4*>(out + obase) = r;
    } else {
#pragma unroll
        for (int j = 0; j < VEC; j++) out[obase + j] = apply_act(acc[j], ACT);
    }
}

// ---------------- VQ ----------------
__global__ void vq_prep(const float* __restrict__ emb)
{
    int k = blockIdx.x * blockDim.x + threadIdx.x;
    if (k == 0) g_loss = 0.0;
    if (k < 512) {
        float s = 0.0f;
#pragma unroll 8
        for (int d = 0; d < 64; d++) { float e = emb[k * 64 + d]; s = fmaf(e, e, s); }
        g_e2[k] = s;
    }
}

__global__ void vq_argmin(const float* __restrict__ emb)
{
    int p = blockIdx.x * blockDim.x + threadIdx.x;
    if (p >= N_POS) return;

    float zr[64];
    const float* zp = g_z + p * 64;
    float z2 = 0.0f;
#pragma unroll
    for (int d = 0; d < 64; d++) { zr[d] = zp[d]; z2 = fmaf(zr[d], zr[d], z2); }

    float best = 3.4e38f;
    int   bi   = 0;
    for (int k = 0; k < 512; k++) {
        const float* ep = emb + k * 64;
        float dot = 0.0f;
#pragma unroll
        for (int d = 0; d < 64; d++) dot = fmaf(zr[d], ep[d], dot);
        float dist = z2 - 2.0f * dot + g_e2[k];
        if (dist < best) { best = dist; bi = k; }   // strict <  => first min (argmin)
    }
    g_idx[p] = bi;
}

__global__ void vq_gather_loss(const float* __restrict__ emb)
{
    int t = blockIdx.x * blockDim.x + threadIdx.x;
    float sq = 0.0f;
    if (t < Z_ELEMS) {
        int p = t >> 6, d = t & 63;
        float qv = emb[g_idx[p] * 64 + d];
        float zv = g_z[t];
        g_q[t] = qv;
        float df = qv - zv;
        sq = df * df;
    }
#pragma unroll
    for (int o = 16; o > 0; o >>= 1) sq += __shfl_down_sync(0xffffffffu, sq, o);
    __shared__ float sm[8];
    int lane = threadIdx.x & 31, wid = threadIdx.x >> 5;
    if (lane == 0) sm[wid] = sq;
    __syncthreads();
    if (wid == 0) {
        float v = (lane < 8) ? sm[lane] : 0.0f;
#pragma unroll
        for (int o = 4; o > 0; o >>= 1) v += __shfl_down_sync(0xffffffffu, v, o);
        if (lane == 0) atomicAdd(&g_loss, (double)v);
    }
}

// ---------------- tail: loss scalar + idx-as-float ----------------
__global__ void write_tail(float* __restrict__ out, int out_size)
{
    int t = blockIdx.x * blockDim.x + threadIdx.x;
    if (t == 0 && Y_SIZE < out_size)
        out[Y_SIZE] = (float)(0.25 * g_loss / (double)Z_ELEMS);
    int off = Y_SIZE + 1 + t;
    if (t < N_POS && off < out_size)
        out[off] = (float)g_idx[t];
}

// ---------------------------------------------------------------------------
extern "C" void kernel_launch(void* const* d_in, const int* in_sizes, int n_in,
                              void* d_out, int out_size)
{
    const float* x    = (const float*)d_in[0];
    const float* ew1  = (const float*)d_in[1];  const float* eb1 = (const float*)d_in[2];
    const float* ew2  = (const float*)d_in[3];  const float* eb2 = (const float*)d_in[4];
    const float* ew3  = (const float*)d_in[5];  const float* eb3 = (const float*)d_in[6];
    const float* ew4  = (const float*)d_in[7];  const float* eb4 = (const float*)d_in[8];
    const float* emb  = (const float*)d_in[9];
    const float* dw1  = (const float*)d_in[10]; const float* db1 = (const float*)d_in[11];
    const float* dw2  = (const float*)d_in[12]; const float* db2 = (const float*)d_in[13];
    const float* dw3  = (const float*)d_in[14]; const float* db3 = (const float*)d_in[15];
    const float* dw4  = (const float*)d_in[16]; const float* db4 = (const float*)d_in[17];
    float* out = (float*)d_out;

    float *a1, *a2, *a3;
    cudaGetSymbolAddress((void**)&a1, g_a1);
    cudaGetSymbolAddress((void**)&a2, g_a2);
    cudaGetSymbolAddress((void**)&a3, g_a3);
    float *zb, *qb;
    cudaGetSymbolAddress((void**)&zb, g_z);
    cudaGetSymbolAddress((void**)&qb, g_q);

    const int TPB = 256;
    auto blocks = [](long long tot, int tpb) { return (unsigned)((tot + tpb - 1) / tpb); };

    // prep: e2 + loss=0
    vq_prep<<<2, TPB>>>(emb);

    // ---- encoder ----
    // enc1: 128x128x3 -> 64x64x32, k4 s2 pad1, relu
    conv_fwd<4,2,1,3,32,ACT_RELU,128,128,64,64,4>
        <<<blocks(128LL*64*64*32/4, TPB), TPB>>>(x, ew1, eb1, a1);
    // enc2: 64x64x32 -> 32x32x64
    conv_fwd<4,2,1,32,64,ACT_RELU,64,64,32,32,4>
        <<<blocks(128LL*32*32*64/4, TPB), TPB>>>(a1, ew2, eb2, a2);
    // enc3: 32x32x64 -> 16x16x128
    conv_fwd<4,2,1,64,128,ACT_RELU,32,32,16,16,4>
        <<<blocks(128LL*16*16*128/4, TPB), TPB>>>(a2, ew3, eb3, a3);
    // enc4: 16x16x128 -> 16x16x64, k2 s1, SAME pad_lo=0 (pad_hi=1), no act
    conv_fwd<2,1,0,128,64,ACT_NONE,16,16,16,16,4>
        <<<blocks(128LL*16*16*64/4, TPB), TPB>>>(a3, ew4, eb4, zb);

    // ---- vector quantizer ----
    vq_argmin<<<blocks(N_POS, TPB), TPB>>>(emb);
    vq_gather_loss<<<blocks(Z_ELEMS, TPB), TPB>>>(emb);

    // ---- decoder (conv_transpose, SAME) ----
    // dec1: 16x16x64 -> 16x16x128, k2 s1, pad_a=1
    convT_fwd<2,1,1,64,128,ACT_RELU,16,16,16,16,4>
        <<<blocks(128LL*16*16*128/4, TPB), TPB>>>(qb, dw1, db1, a3);
    // dec2: 16x16x128 -> 32x32x64, k4 s2, pad_a=2
    convT_fwd<4,2,2,128,64,ACT_RELU,16,16,32,32,4>
        <<<blocks(128LL*32*32*64/4, TPB), TPB>>>(a3, dw2, db2, a2);
    // dec3: 32x32x64 -> 64x64x32
    convT_fwd<4,2,2,64,32,ACT_RELU,32,32,64,64,4>
        <<<blocks(128LL*64*64*32/4, TPB), TPB>>>(a2, dw3, db3, a1);
    // dec4: 64x64x32 -> 128x128x3, sigmoid, writes y directly into d_out
    convT_fwd<4,2,2,32,3,ACT_SIG,64,64,128,128,1>
        <<<blocks(128LL*128*128*3, TPB), TPB>>>(a1, dw4, db4, out);

    // ---- loss + idx tail ----
    write_tail<<<blocks(N_POS, TPB), TPB>>>(out, out_size);
}

// round 3
// speedup vs baseline: 4.0360x; 4.0360x over previous
#include <cuda_runtime.h>
#include <math.h>

#define ACT_NONE 0
#define ACT_RELU 1
#define ACT_SIG  2

// ---- scratch (device globals; reused encoder<->decoder) ----
__device__ float  g_a1[128 * 64 * 64 * 32];
__device__ float  g_a2[128 * 32 * 32 * 64];
__device__ float  g_a3[128 * 16 * 16 * 128];
__device__ float  g_z [128 * 16 * 16 * 64];
__device__ float  g_q [128 * 16 * 16 * 64];
__device__ int    g_idx[128 * 256];
__device__ float  g_e2[512];
__device__ double g_loss;

static const int Y_SIZE  = 128 * 128 * 128 * 3;
static const int N_POS   = 128 * 16 * 16;
static const int Z_ELEMS = N_POS * 64;

__host__ __device__ constexpr int ilog2c(int v) {
    int l = 0; while (v > 1) { v >>= 1; ++l; } return l;
}

__device__ __forceinline__ float actf(float v, int ACT) {
    if (ACT == ACT_RELU) return fmaxf(v, 0.0f);
    if (ACT == ACT_SIG)  return 1.0f / (1.0f + expf(-v));
    return v;
}

// ===========================================================================
// GEMM-tiled conv. MODE 0: fwd conv (stride S, pad P)
//                  MODE 1: convT stride 1 (pad_a P)
//                  MODE 2: convT stride 2 (pad_a P), parity sub-conv via blockIdx.z
// Block computes BM x BN output tile; thread computes 8(m) x 4(n) registers.
// ===========================================================================
template<int BN, int IC, int OC, int ACT, int IH, int IW, int OH, int OW,
         int K, int MODE, int S, int P>
__global__ void __launch_bounds__(256, 2)
conv_gemm(const float* __restrict__ in, const float* __restrict__ w,
          const float* __restrict__ bias, float* __restrict__ out)
{
    constexpr int TN   = BN / 4;        // threads along n
    constexpr int TM   = 256 / TN;      // threads along m
    constexpr int BM   = TM * 8;        // rows per block
    constexpr int PADK = 36;            // 32 + 4 pad (keeps 16B align)
    constexpr int EOH  = (MODE == 2) ? OH / 2 : OH;
    constexpr int EOW  = (MODE == 2) ? OW / 2 : OW;
    constexpr int LW   = ilog2c(EOW);
    constexpr int LH   = ilog2c(EOH);
    constexpr int NT   = (MODE == 2) ? 4 : K * K;
    constexpr int WROW = BN / 4;

    __shared__ float sIn[BM * PADK];
    __shared__ float sW[32 * BN];
    __shared__ const float* sPtr[BM];

    const int tid  = threadIdx.x;
    const int mblk = blockIdx.x * BM;
    const int ocb  = blockIdx.y * BN;
    int py = 0, px = 0;
    if (MODE == 2) { py = blockIdx.z >> 1; px = blockIdx.z & 1; }

    const int tn = tid % TN;
    const int tm = tid / TN;

    float acc[8][4];
#pragma unroll
    for (int i = 0; i < 8; i++)
#pragma unroll
        for (int j = 0; j < 4; j++) acc[i][j] = 0.0f;

    for (int t = 0; t < NT; t++) {
        int ky, kx;
        if (MODE == 2) {
            ky = ((P + py) & 1) + 2 * (t >> 1);
            kx = ((P + px) & 1) + 2 * (t & 1);
        } else {
            ky = t / K; kx = t - ky * K;
        }

        if (tid < BM) {
            int m  = mblk + tid;
            int ox = m & (EOW - 1);
            int r1 = m >> LW;
            int oy = r1 & (EOH - 1);
            int n  = r1 >> LH;
            int iy, ix;
            if (MODE == 0)      { iy = oy * S - P + ky; ix = ox * S - P + kx; }
            else if (MODE == 1) { iy = oy + ky - P;     ix = ox + kx - P; }
            else {              // MODE 2: full coords even by parity construction
                iy = (2 * oy + py + ky - P) >> 1;
                ix = (2 * ox + px + kx - P) >> 1;
            }
            bool v = (iy >= 0) && (iy < IH) && (ix >= 0) && (ix < IW);
            sPtr[tid] = v ? (in + ((n * IH + iy) * IW + ix) * IC) : (const float*)0;
        }

        const float* wt = w + ((ky * K + kx) * IC) * OC + ocb;

        for (int icb = 0; icb < IC; icb += 32) {
            __syncthreads();
            // stage input tile [BM][32] (zero-fill invalid rows)
#pragma unroll
            for (int u = 0; u < BM / 32; u++) {
                int j  = tid + u * 256;
                int m  = j >> 3, c4 = j & 7;
                const float* p = sPtr[m];
                float4 v4 = make_float4(0.f, 0.f, 0.f, 0.f);
                if (p) v4 = *reinterpret_cast<const float4*>(p + icb + c4 * 4);
                *reinterpret_cast<float4*>(&sIn[m * PADK + c4 * 4]) = v4;
            }
            // stage weight tile [32][BN]
#pragma unroll
            for (int u = 0; u < (32 * BN) / 1024; u++) {
                int j  = tid + u * 256;
                int r  = j / WROW, c4 = j % WROW;
                float4 wv = *reinterpret_cast<const float4*>(wt + (icb + r) * OC + c4 * 4);
                *reinterpret_cast<float4*>(&sW[r * BN + c4 * 4]) = wv;
            }
            __syncthreads();

#pragma unroll
            for (int kk = 0; kk < 32; kk += 4) {
                float4 b0 = *reinterpret_cast<const float4*>(&sW[(kk + 0) * BN + tn * 4]);
                float4 b1 = *reinterpret_cast<const float4*>(&sW[(kk + 1) * BN + tn * 4]);
                float4 b2 = *reinterpret_cast<const float4*>(&sW[(kk + 2) * BN + tn * 4]);
                float4 b3 = *reinterpret_cast<const float4*>(&sW[(kk + 3) * BN + tn * 4]);
#pragma unroll
                for (int i = 0; i < 8; i++) {
                    float4 a = *reinterpret_cast<const float4*>(&sIn[(tm * 8 + i) * PADK + kk]);
                    acc[i][0] = fmaf(a.x, b0.x, acc[i][0]);
                    acc[i][1] = fmaf(a.x, b0.y, acc[i][1]);
                    acc[i][2] = fmaf(a.x, b0.z, acc[i][2]);
                    acc[i][3] = fmaf(a.x, b0.w, acc[i][3]);
                    acc[i][0] = fmaf(a.y, b1.x, acc[i][0]);
                    acc[i][1] = fmaf(a.y, b1.y, acc[i][1]);
                    acc[i][2] = fmaf(a.y, b1.z, acc[i][2]);
                    acc[i][3] = fmaf(a.y, b1.w, acc[i][3]);
                    acc[i][0] = fmaf(a.z, b2.x, acc[i][0]);
                    acc[i][1] = fmaf(a.z, b2.y, acc[i][1]);
                    acc[i][2] = fmaf(a.z, b2.z, acc[i][2]);
                    acc[i][3] = fmaf(a.z, b2.w, acc[i][3]);
                    acc[i][0] = fmaf(a.w, b3.x, acc[i][0]);
                    acc[i][1] = fmaf(a.w, b3.y, acc[i][1]);
                    acc[i][2] = fmaf(a.w, b3.z, acc[i][2]);
                    acc[i][3] = fmaf(a.w, b3.w, acc[i][3]);
                }
            }
        }
    }

    // epilogue
    float4 bv = *reinterpret_cast<const float4*>(bias + ocb + tn * 4);
#pragma unroll
    for (int i = 0; i < 8; i++) {
        int m = mblk + tm * 8 + i;
        int off;
        if (MODE == 2) {
            int ox = m & (EOW - 1);
            int r1 = m >> LW;
            int oy = r1 & (EOH - 1);
            int n  = r1 >> LH;
            off = ((n * OH + 2 * oy + py) * OW + 2 * ox + px) * OC + ocb + tn * 4;
        } else {
            off = m * OC + ocb + tn * 4;
        }
        float4 r;
        r.x = actf(acc[i][0] + bv.x, ACT);
        r.y = actf(acc[i][1] + bv.y, ACT);
        r.z = actf(acc[i][2] + bv.z, ACT);
        r.w = actf(acc[i][3] + bv.w, ACT);
        *reinterpret_cast<float4*>(out + off) = r;
    }
}

// ===========================================================================
// enc1: 128x128x3 -> 64x64x32, k4 s2 pad1, relu. IC=3 -> direct, 8 oc/thread.
// ===========================================================================
__global__ void __launch_bounds__(256)
enc1_kernel(const float* __restrict__ x, const float* __restrict__ w,
            const float* __restrict__ bias, float* __restrict__ out)
{
    int t = blockIdx.x * 256 + threadIdx.x;     // 128*64*64*4 threads
    int g = t & 3; int pos = t >> 2;
    int ox = pos & 63; int r1 = pos >> 6;
    int oy = r1 & 63;  int n  = r1 >> 6;
    int oc = g * 8;

    float acc[8];
#pragma unroll
    for (int j = 0; j < 8; j++) acc[j] = bias[oc + j];

#pragma unroll
    for (int ky = 0; ky < 4; ky++) {
        int iy = oy * 2 - 1 + ky;
        if ((unsigned)iy >= 128u) continue;
#pragma unroll
        for (int kx = 0; kx < 4; kx++) {
            int ix = ox * 2 - 1 + kx;
            if ((unsigned)ix >= 128u) continue;
            const float* ip = x + ((n * 128 + iy) * 128 + ix) * 3;
            const float* wp = w + ((ky * 4 + kx) * 3) * 32 + oc;
#pragma unroll
            for (int ic = 0; ic < 3; ic++) {
                float iv = ip[ic];
                float4 w0 = *reinterpret_cast<const float4*>(wp + ic * 32);
                float4 w1 = *reinterpret_cast<const float4*>(wp + ic * 32 + 4);
                acc[0] = fmaf(iv, w0.x, acc[0]); acc[1] = fmaf(iv, w0.y, acc[1]);
                acc[2] = fmaf(iv, w0.z, acc[2]); acc[3] = fmaf(iv, w0.w, acc[3]);
                acc[4] = fmaf(iv, w1.x, acc[4]); acc[5] = fmaf(iv, w1.y, acc[5]);
                acc[6] = fmaf(iv, w1.z, acc[6]); acc[7] = fmaf(iv, w1.w, acc[7]);
            }
        }
    }
    float4 r0, r1v;
    r0.x = fmaxf(acc[0], 0.f); r0.y = fmaxf(acc[1], 0.f);
    r0.z = fmaxf(acc[2], 0.f); r0.w = fmaxf(acc[3], 0.f);
    r1v.x = fmaxf(acc[4], 0.f); r1v.y = fmaxf(acc[5], 0.f);
    r1v.z = fmaxf(acc[6], 0.f); r1v.w = fmaxf(acc[7], 0.f);
    float* op = out + pos * 32 + oc;
    *reinterpret_cast<float4*>(op)     = r0;
    *reinterpret_cast<float4*>(op + 4) = r1v;
}

// ===========================================================================
// dec4: convT 64x64x32 -> 128x128x3, k4 s2 pad_a=2, sigmoid.
// Thread computes 4 parities x 3 channels from a 3x3 input window.
// ===========================================================================
__global__ void __launch_bounds__(256)
dec4_kernel(const float* __restrict__ in, const float* __restrict__ w,
            const float* __restrict__ bias, float* __restrict__ out)
{
    __shared__ float sw[4][4][3][32];   // [ky][kx][c][ic]
    int tid = threadIdx.x;
    for (int j = tid; j < 4 * 4 * 32 * 3; j += 256) {
        int c = j % 3; int r = j / 3;
        int ic = r % 32; int kk = r / 32;
        int ky = kk >> 2, kx = kk & 3;
        sw[ky][kx][c][ic] = w[j];
    }
    __syncthreads();

    int t = blockIdx.x * 256 + tid;      // 128*64*64 threads
    int ox2 = t & 63; int r1 = t >> 6;
    int oy2 = r1 & 63; int n = r1 >> 6;

    float acc[2][2][3];
#pragma unroll
    for (int py = 0; py < 2; py++)
#pragma unroll
        for (int px = 0; px < 2; px++)
#pragma unroll
            for (int c = 0; c < 3; c++) acc[py][px][c] = bias[c];

#pragma unroll
    for (int dy = -1; dy <= 1; dy++) {
        int iy = oy2 + dy;
        if ((unsigned)iy >= 64u) continue;
#pragma unroll
        for (int dx = -1; dx <= 1; dx++) {
            int ix = ox2 + dx;
            if ((unsigned)ix >= 64u) continue;
            const float* ip = in + ((n * 64 + iy) * 64 + ix) * 32;
            float iv[32];
#pragma unroll
            for (int q = 0; q < 8; q++)
                *reinterpret_cast<float4*>(&iv[q * 4]) =
                    *reinterpret_cast<const float4*>(ip + q * 4);
#pragma unroll
            for (int py = 0; py < 2; py++)
#pragma unroll
                for (int a = 0; a < 2; a++) {
                    if (py + a - 1 != dy) continue;       // compile-time pruned
                    int ky = py + 2 * a;
#pragma unroll
                    for (int px = 0; px < 2; px++)
#pragma unroll
                        for (int bq = 0; bq < 2; bq++) {
                            if (px + bq - 1 != dx) continue;
                            int kx = px + 2 * bq;
#pragma unroll
                            for (int c = 0; c < 3; c++) {
#pragma unroll
                                for (int ic = 0; ic < 32; ic++)
                                    acc[py][px][c] =
                                        fmaf(iv[ic], sw[ky][kx][c][ic], acc[py][px][c]);
                            }
                        }
                }
        }
    }

#pragma unroll
    for (int py = 0; py < 2; py++)
#pragma unroll
        for (int px = 0; px < 2; px++) {
            int base = ((n * 128 + 2 * oy2 + py) * 128 + 2 * ox2 + px) * 3;
#pragma unroll
            for (int c = 0; c < 3; c++)
                out[base + c] = 1.0f / (1.0f + expf(-acc[py][px][c]));
        }
}

// ---------------- VQ ----------------
__global__ void vq_prep(const float* __restrict__ emb)
{
    int k = blockIdx.x * blockDim.x + threadIdx.x;
    if (k == 0) g_loss = 0.0;
    if (k < 512) {
        float s = 0.0f;
#pragma unroll 8
        for (int d = 0; d < 64; d++) { float e = emb[k * 64 + d]; s = fmaf(e, e, s); }
        g_e2[k] = s;
    }
}

__global__ void __launch_bounds__(256)
vq_argmin(const float* __restrict__ emb)
{
    __shared__ float sE[32 * 64];
    __shared__ float sE2[32];
    int tid = threadIdx.x;
    int p = blockIdx.x * 256 + tid;

    float zr[64];
    const float* zp = g_z + p * 64;
#pragma unroll
    for (int q = 0; q < 16; q++)
        *reinterpret_cast<float4*>(&zr[q * 4]) =
            *reinterpret_cast<const float4*>(zp + q * 4);

    float best = 3.4e38f;
    int   bi   = 0;
    for (int kb = 0; kb < 512; kb += 32) {
        __syncthreads();
#pragma unroll
        for (int u = 0; u < 2; u++) {
            int j = tid + u * 256;
            *reinterpret_cast<float4*>(&sE[j * 4]) =
                *reinterpret_cast<const float4*>(emb + kb * 64 + j * 4);
        }
        if (tid < 32) sE2[tid] = g_e2[kb + tid];
        __syncthreads();
#pragma unroll 4
        for (int k = 0; k < 32; k++) {
            float dot = 0.0f;
#pragma unroll
            for (int q = 0; q < 16; q++) {
                float4 e = *reinterpret_cast<const float4*>(&sE[k * 64 + q * 4]);
                dot = fmaf(zr[q * 4 + 0], e.x, dot);
                dot = fmaf(zr[q * 4 + 1], e.y, dot);
                dot = fmaf(zr[q * 4 + 2], e.z, dot);
                dot = fmaf(zr[q * 4 + 3], e.w, dot);
            }
            float dist = sE2[k] - 2.0f * dot;   // z2 dropped (uniform shift)
            if (dist < best) { best = dist; bi = kb + k; }
        }
    }
    g_idx[p] = bi;
}

__global__ void vq_gather_loss(const float* __restrict__ emb)
{
    int t = blockIdx.x * blockDim.x + threadIdx.x;
    float sq = 0.0f;
    if (t < Z_ELEMS) {
        int p = t >> 6, d = t & 63;
        float qv = emb[g_idx[p] * 64 + d];
        float zv = g_z[t];
        g_q[t] = qv;
        float df = qv - zv;
        sq = df * df;
    }
#pragma unroll
    for (int o = 16; o > 0; o >>= 1) sq += __shfl_down_sync(0xffffffffu, sq, o);
    __shared__ float sm[8];
    int lane = threadIdx.x & 31, wid = threadIdx.x >> 5;
    if (lane == 0) sm[wid] = sq;
    __syncthreads();
    if (wid == 0) {
        float v = (lane < 8) ? sm[lane] : 0.0f;
#pragma unroll
        for (int o = 4; o > 0; o >>= 1) v += __shfl_down_sync(0xffffffffu, v, o);
        if (lane == 0) atomicAdd(&g_loss, (double)v);
    }
}

__global__ void write_tail(float* __restrict__ out, int out_size)
{
    int t = blockIdx.x * blockDim.x + threadIdx.x;
    if (t == 0 && Y_SIZE < out_size)
        out[Y_SIZE] = (float)(0.25 * g_loss / (double)Z_ELEMS);
    int off = Y_SIZE + 1 + t;
    if (t < N_POS && off < out_size)
        out[off] = (float)g_idx[t];
}

// ---------------------------------------------------------------------------
extern "C" void kernel_launch(void* const* d_in, const int* in_sizes, int n_in,
                              void* d_out, int out_size)
{
    const float* x   = (const float*)d_in[0];
    const float* ew1 = (const float*)d_in[1];  const float* eb1 = (const float*)d_in[2];
    const float* ew2 = (const float*)d_in[3];  const float* eb2 = (const float*)d_in[4];
    const float* ew3 = (const float*)d_in[5];  const float* eb3 = (const float*)d_in[6];
    const float* ew4 = (const float*)d_in[7];  const float* eb4 = (const float*)d_in[8];
    const float* emb = (const float*)d_in[9];
    const float* dw1 = (const float*)d_in[10]; const float* db1 = (const float*)d_in[11];
    const float* dw2 = (const float*)d_in[12]; const float* db2 = (const float*)d_in[13];
    const float* dw3 = (const float*)d_in[14]; const float* db3 = (const float*)d_in[15];
    const float* dw4 = (const float*)d_in[16]; const float* db4 = (const float*)d_in[17];
    float* out = (float*)d_out;

    float *a1, *a2, *a3, *zb, *qb;
    cudaGetSymbolAddress((void**)&a1, g_a1);
    cudaGetSymbolAddress((void**)&a2, g_a2);
    cudaGetSymbolAddress((void**)&a3, g_a3);
    cudaGetSymbolAddress((void**)&zb, g_z);
    cudaGetSymbolAddress((void**)&qb, g_q);

    vq_prep<<<2, 256>>>(emb);

    // ---- encoder ----
    enc1_kernel<<<128 * 64 * 64 * 4 / 256, 256>>>(x, ew1, eb1, a1);
    // enc2: 64x64x32 -> 32x32x64, k4 s2 p1
    conv_gemm<64, 32, 64, ACT_RELU, 64, 64, 32, 32, 4, 0, 2, 1>
        <<<dim3(1024, 1, 1), 256>>>(a1, ew2, eb2, a2);
    // enc3: 32x32x64 -> 16x16x128
    conv_gemm<64, 64, 128, ACT_RELU, 32, 32, 16, 16, 4, 0, 2, 1>
        <<<dim3(256, 2, 1), 256>>>(a2, ew3, eb3, a3);
    // enc4: 16x16x128 -> 16x16x64, k2 s1 p0
    conv_gemm<64, 128, 64, ACT_NONE, 16, 16, 16, 16, 2, 0, 1, 0>
        <<<dim3(256, 1, 1), 256>>>(a3, ew4, eb4, zb);

    // ---- VQ ----
    vq_argmin<<<N_POS / 256, 256>>>(emb);
    vq_gather_loss<<<(Z_ELEMS + 255) / 256, 256>>>(emb);

    // ---- decoder ----
    // dec1: convT k2 s1 pad_a=1: 16x16x64 -> 16x16x128
    conv_gemm<64, 64, 128, ACT_RELU, 16, 16, 16, 16, 2, 1, 1, 1>
        <<<dim3(256, 2, 1), 256>>>(qb, dw1, db1, a3);
    // dec2: convT k4 s2 pad_a=2: 16x16x128 -> 32x32x64 (4 parities)
    conv_gemm<64, 128, 64, ACT_RELU, 16, 16, 32, 32, 4, 2, 2, 2>
        <<<dim3(256, 1, 4), 256>>>(a3, dw2, db2, a2);
    // dec3: convT k4 s2 pad_a=2: 32x32x64 -> 64x64x32 (4 parities)
    conv_gemm<32, 64, 32, ACT_RELU, 32, 32, 64, 64, 4, 2, 2, 2>
        <<<dim3(512, 1, 4), 256>>>(a2, dw3, db3, a1);
    // dec4: convT k4 s2 pad_a=2: 64x64x32 -> 128x128x3, sigmoid -> d_out
    dec4_kernel<<<128 * 64 * 64 / 256, 256>>>(a1, dw4, db4, out);

    write_tail<<<(N_POS + 255) / 256, 256>>>(out, out_size);
}